// round 13
// baseline (speedup 1.0000x reference)
#include <cuda_runtime.h>

// QuantumRecurrentUnit — closed-form reduction, 2 lanes per chain,
// PACKED f32x2 polynomial sincos (FFMA2) to beat the rt_SMSP=2 FFMA cap.
//
// Per step: theta_q = prev_q + x_q;  P_m = prod_{q<=m} cos theta_q;
//   out_m = cos(w_m)*P_m - sin(w_m)*sin(theta_m)*sin(theta_{m+1})  (m<5)
//   out_5 = cos(w_5)*P_5 - sin(w_5)*sin(theta_5)
//
// R13: R12 was per-SMSP FMA-pipe throughput bound (FFMA rt_SMSP=2, one warp
// per SMSP, ~70 FFMA/step -> ~140 cyc issue floor; observed 212 cyc/step).
// Pack with fma.rn.f32x2 (sm_100+): wires A,B evaluated in one packed
// sincos; wire C packs its sin-poly against its cos-poly. Single-float-pi
// range reduction (|k|<=3 -> err 2.6e-7). ~41 fma-pipe instrs/step.

#define NQ 6
#define T_STEPS 1024
#define C_IN 16
#define PF 8   // prefetch ring depth in steps (divides T_STEPS)

typedef unsigned long long u64;

__device__ __forceinline__ u64 pk2(float lo, float hi) {
    u64 r; asm("mov.b64 %0, {%1, %2};" : "=l"(r) : "f"(lo), "f"(hi)); return r;
}
__device__ __forceinline__ void upk2(u64 v, float& lo, float& hi) {
    asm("mov.b64 {%0, %1}, %2;" : "=f"(lo), "=f"(hi) : "l"(v));
}
__device__ __forceinline__ u64 fma2v(u64 a, u64 b, u64 c) {
    u64 d; asm("fma.rn.f32x2 %0, %1, %2, %3;" : "=l"(d) : "l"(a), "l"(b), "l"(c)); return d;
}
__device__ __forceinline__ u64 add2v(u64 a, u64 b) {
    u64 d; asm("add.rn.f32x2 %0, %1, %2;" : "=l"(d) : "l"(a), "l"(b)); return d;
}
__device__ __forceinline__ u64 mul2v(u64 a, u64 b) {
    u64 d; asm("mul.rn.f32x2 %0, %1, %2;" : "=l"(d) : "l"(a), "l"(b)); return d;
}
__device__ __forceinline__ float fxor(float v, unsigned s) {
    return __uint_as_float(__float_as_uint(v) ^ s);
}

// Polynomial coefficients (Taylor, [-pi/2, pi/2]).
#define S5f (-2.5052108385e-8f)
#define S4f ( 2.7557319224e-6f)
#define S3f (-1.9841269841e-4f)
#define S2f ( 8.3333333333e-3f)
#define S1f (-1.6666666667e-1f)
#define C5f (-2.7557319224e-7f)
#define C4f ( 2.4801587302e-5f)
#define C3f (-1.3888888889e-3f)
#define C2f ( 4.1666666667e-2f)
#define C1f (-0.5f)
#define INVPIf ( 0.3183098861837907f)
#define MAGICf ( 12582912.0f)      // 1.5 * 2^23
#define PIF    ( 3.14159274101257f) // float-rounded pi

__global__ void __launch_bounds__(32, 1)
qru_kernel(const float* __restrict__ x, const float* __restrict__ w,
           float* __restrict__ out, int B) {
    int gt   = blockIdx.x * 32 + threadIdx.x;
    int pair = gt >> 1;          // chain index
    int r    = gt & 1;           // 0: wires 0-2, 1: wires 3-5
    if (pair >= B) return;
    // Both lanes of a pair are jointly active/inactive -> pair-local bfly
    // under the active mask is convergence-safe.
    unsigned mask = __activemask();

    // Packed constant registers (hoisted once).
    const u64 INV2 = pk2(INVPIf, INVPIf);
    const u64 MAG2 = pk2(MAGICf, MAGICf);
    const u64 NMG2 = pk2(-MAGICf, -MAGICf);
    const u64 NPI2 = pk2(-PIF, -PIF);
    const u64 ONE2 = pk2(1.0f, 1.0f);
    const u64 S5p = pk2(S5f, S5f), S4p = pk2(S4f, S4f), S3p = pk2(S3f, S3f),
              S2p = pk2(S2f, S2f), S1p = pk2(S1f, S1f);
    const u64 C5p = pk2(C5f, C5f), C4p = pk2(C4f, C4f), C3p = pk2(C3f, C3f),
              C2p = pk2(C2f, C2f), C1p = pk2(C1f, C1f);
    const u64 SC5 = pk2(S5f, C5f), SC4 = pk2(S4f, C4f), SC3 = pk2(S3f, C3f),
              SC2 = pk2(S2f, C2f), SC1 = pk2(S1f, C1f);

    // This lane's 3 weights (once; accuracy non-critical path).
    float cwA, swA, cwB, swB, cwC, swC;
    __sincosf(__ldg(w + r * 3 + 0), &swA, &cwA);
    __sincosf(__ldg(w + r * 3 + 1), &swB, &cwB);
    __sincosf(__ldg(w + r * 3 + 2), &swC, &cwC);
    float nswA = -swA, nswB = -swB, nswC = -swC;

    const float*  xb  = x + (size_t)pair * (T_STEPS * C_IN);
    const float4* xp4 = reinterpret_cast<const float4*>(xb);   // row t: xp4 + t*4
    const float2* xp2 = reinterpret_cast<const float2*>(xb);   // x4,x5: xp2[t*8+2]
    float* __restrict__ op = out + (size_t)pair * (T_STEPS * NQ);

    u64   pAB = pk2(0.f, 0.f);   // packed (pA, pB)
    float pC  = 0.f;

    // Prefetch ring (both lanes of a pair load same addresses: broadcast).
    float4 rA[PF];
    float2 rB[PF];
    #pragma unroll
    for (int d = 0; d < PF; d++) {
        rA[d] = __ldg(xp4 + d * 4);
        rB[d] = __ldg(xp2 + d * 8 + 2);
    }

    const float onef = 1.0f;

    for (int tb = 0; tb < T_STEPS; tb += PF) {
        bool more = (tb + PF) < T_STEPS;
        #pragma unroll
        for (int u = 0; u < PF; u++) {
            const int t = tb + u;
            // Per-lane inputs: lane0 -> x0,x1,x2 ; lane1 -> x3,x4,x5.
            float xA = r ? rA[u].w : rA[u].x;
            float xB = r ? rB[u].x : rA[u].y;
            float xC = r ? rB[u].y : rA[u].z;

            if (more) {   // refill slot for step t+PF (covers DRAM latency)
                rA[u] = __ldg(xp4 + (t + PF) * 4);
                rB[u] = __ldg(xp2 + (t + PF) * 8 + 2);
            }

            // ---- packed sincos of (thA, thB) ----
            u64 th2 = add2v(pAB, pk2(xA, xB));
            u64 fk2 = fma2v(th2, INV2, MAG2);
            float fkl, fkh; upk2(fk2, fkl, fkh);
            unsigned sgA = __float_as_uint(fkl) << 31;
            unsigned sgB = __float_as_uint(fkh) << 31;
            u64 k2 = add2v(fk2, NMG2);
            u64 rr = fma2v(k2, NPI2, th2);       // residual in [-pi/2, pi/2]
            u64 q2 = mul2v(rr, rr);
            u64 ts = fma2v(S5p, q2, S4p);
            ts = fma2v(ts, q2, S3p);
            ts = fma2v(ts, q2, S2p);
            ts = fma2v(ts, q2, S1p);
            u64 sm = mul2v(ts, q2);
            u64 sv2 = fma2v(sm, rr, rr);         // (sinA, sinB) pre-sign
            u64 tc = fma2v(C5p, q2, C4p);
            tc = fma2v(tc, q2, C3p);
            tc = fma2v(tc, q2, C2p);
            tc = fma2v(tc, q2, C1p);
            u64 cv2 = fma2v(tc, q2, ONE2);       // (cosA, cosB) pre-sign
            float sA0, sB0, cA0, cB0;
            upk2(sv2, sA0, sB0); upk2(cv2, cA0, cB0);
            float sA = fxor(sA0, sgA), cA = fxor(cA0, sgA);
            float sB = fxor(sB0, sgB), cB = fxor(cB0, sgB);

            // ---- sin/cos-packed sincos of thC ----
            float thC = pC + xC;
            float fkc = fmaf(thC, INVPIf, MAGICf);
            unsigned sgC = __float_as_uint(fkc) << 31;
            float kc = fkc - MAGICf;
            float rc = fmaf(kc, -PIF, thC);
            float qc = rc * rc;
            u64 qcp = pk2(qc, qc);
            u64 tsc = fma2v(SC5, qcp, SC4);
            tsc = fma2v(tsc, qcp, SC3);
            tsc = fma2v(tsc, qcp, SC2);
            tsc = fma2v(tsc, qcp, SC1);
            u64 vc = fma2v(tsc, qcp, ONE2);      // (1+q*ts, cosC-pre)
            float vs, cC0; upk2(vc, vs, cC0);
            float sC = fxor(vs * rc, sgC);
            float cC = fxor(cC0, sgC);

            // ---- coupling + outputs (unchanged algebra) ----
            float t1  = cA * cB;
            float t2  = t1 * cC;                 // lane0: P2 = c0c1c2
            float send = r ? sA : t2;            // lane1 sends s3, lane0 sends P2
            float recv = __shfl_xor_sync(mask, send, 1);

            float mul = r ? recv : onef;         // lane1: P2 from lane0
            float PA  = mul * cA;
            float PB  = mul * t1;
            float PC  = mul * t2;

            float sAB = sA * sB;
            float sBC = sB * sC;
            float sCl = sC * (r ? onef : recv);  // lane0: s2*s3, lane1: s5

            float pA = fmaf(cwA, PA, nswA * sAB);
            float pB = fmaf(cwB, PB, nswB * sBC);
            pC       = fmaf(cwC, PC, nswC * sCl);
            pAB = pk2(pA, pB);

            // Store 12B per lane, contiguous across the pair (24B per chain).
            // lane0: {pA,pB} @ elem 0, pC @ elem 2  (byte 24t    : 8-aligned)
            // lane1: {pB,pC} @ elem 4, pA @ elem 3  (byte 24t+16 : 8-aligned)
            float* o = op + t * NQ;
            float2 v2 = r ? make_float2(pB, pC) : make_float2(pA, pB);
            *reinterpret_cast<float2*>(o + (r ? 4 : 0)) = v2;
            o[r ? 3 : 2] = r ? pA : pC;
        }
    }
}

extern "C" void kernel_launch(void* const* d_in, const int* in_sizes, int n_in,
                              void* d_out, int out_size) {
    // Inputs per metadata order: x (B*1024*16 f32), weight (6 f32).
    const float* x = (const float*)d_in[0];
    const float* w = (const float*)d_in[1];
    if (n_in >= 2 && in_sizes[0] == NQ) {  // defensive: identify by size
        const float* tmp = x; x = w; w = tmp;
    }
    float* out = (float*)d_out;

    int B = out_size / (T_STEPS * NQ);
    int threads = 2 * B;                       // 2 lanes per chain
    int blocks  = (threads + 31) / 32;         // 1 warp per block -> spread over SMs
    qru_kernel<<<blocks, 32>>>(x, w, out, B);
}